// round 16
// baseline (speedup 1.0000x reference)
#include <cuda_runtime.h>
#include <cuda_bf16.h>
#include <cstddef>
#include <cstdint>

// Problem constants
#define NTOK 8192   // N
#define BB   32     // batch
#define GD   256    // GRU_DIM
#define HD   512    // HAN_DIM
#define ID   128    // INNER_DIM

// ---------------- device scratch (no allocation) ----------------
__device__ float         g_M[NTOK * GD];      // 8 MB: M[j,d]
__device__ __nv_bfloat16 g_WkHi[ID * HD];     // 128 KB: Wk[e,h] hi (k-contig rows)
__device__ __nv_bfloat16 g_WkLo[ID * HD];     // 128 KB
__device__ __nv_bfloat16 g_WqTHi[GD * ID];    // 64 KB: SCALE * WqT[d,e] hi (k-contig rows)
__device__ __nv_bfloat16 g_WqTLo[GD * ID];    // 64 KB

__device__ __forceinline__ uint32_t smem_u32(const void* p) {
    uint32_t a;
    asm("{ .reg .u64 t; cvta.to.shared.u64 t, %1; cvt.u32.u64 %0, t; }" : "=r"(a) : "l"(p));
    return a;
}
__device__ __forceinline__ void ldsm4(uint32_t addr, uint32_t* r) {
    asm volatile("ldmatrix.sync.aligned.m8n8.x4.shared.b16 {%0,%1,%2,%3}, [%4];"
                 : "=r"(r[0]), "=r"(r[1]), "=r"(r[2]), "=r"(r[3]) : "r"(addr));
}
__device__ __forceinline__ void mma16816(float* c, const uint32_t* a, uint32_t b0, uint32_t b1) {
    asm volatile(
        "mma.sync.aligned.m16n8k16.row.col.f32.bf16.bf16.f32 "
        "{%0,%1,%2,%3}, {%4,%5,%6,%7}, {%8,%9}, {%0,%1,%2,%3};"
        : "+f"(c[0]), "+f"(c[1]), "+f"(c[2]), "+f"(c[3])
        : "r"(a[0]), "r"(a[1]), "r"(a[2]), "r"(a[3]), "r"(b0), "r"(b1));
}
__device__ __forceinline__ uint32_t pack_bf2(__nv_bfloat16 lo16, __nv_bfloat16 hi16) {
    __nv_bfloat162 t; t.x = lo16; t.y = hi16;
    return *reinterpret_cast<uint32_t*>(&t);
}
__device__ __forceinline__ void cp16(uint32_t dst, const void* src) {
    asm volatile("cp.async.cg.shared.global [%0], [%1], 16;" :: "r"(dst), "l"(src) : "memory");
}
__device__ __forceinline__ void split_bf(float v, __nv_bfloat16& hi, __nv_bfloat16& lo) {
    hi = __float2bfloat16(v);
    lo = __float2bfloat16(v - __bfloat162float(hi));
}

// ======================= P: split Wk (64 blocks) + transpose/split SCALE*Wq (32 blocks) ========
__global__ __launch_bounds__(256)
void prep_split_kernel(const float* __restrict__ Wq, const float* __restrict__ Wk)
{
    const int tid = threadIdx.x;
    if (blockIdx.x < 64) {
        int idx = blockIdx.x * 256 + tid;               // float4 index, 16384 total
        float4 v = *reinterpret_cast<const float4*>(Wk + 4 * (size_t)idx);
        __nv_bfloat16 hx, lx, hy, ly, hz, lz, hw, lw;
        split_bf(v.x, hx, lx); split_bf(v.y, hy, ly);
        split_bf(v.z, hz, lz); split_bf(v.w, hw, lw);
        *reinterpret_cast<uint32_t*>(g_WkHi + 4 * (size_t)idx)     = pack_bf2(hx, hy);
        *reinterpret_cast<uint32_t*>(g_WkHi + 4 * (size_t)idx + 2) = pack_bf2(hz, hw);
        *reinterpret_cast<uint32_t*>(g_WkLo + 4 * (size_t)idx)     = pack_bf2(lx, ly);
        *reinterpret_cast<uint32_t*>(g_WkLo + 4 * (size_t)idx + 2) = pack_bf2(lz, lw);
    } else {
        __shared__ float s[32][33];
        const int b  = blockIdx.x - 64;   // 0..31
        const int e0 = (b & 3) * 32;
        const int d0 = (b >> 2) * 32;
        const int r  = tid >> 5;          // 0..7
        const int c  = tid & 31;
        const float SCALE = 0.08838834764831845f;  // 128^-0.5
#pragma unroll
        for (int i = 0; i < 4; i++)
            s[r + i * 8][c] = Wq[(size_t)(e0 + r + i * 8) * GD + d0 + c];   // s[e][d]
        __syncthreads();
#pragma unroll
        for (int i = 0; i < 4; i++) {
            int dl = r + i * 8;
            float v = s[c][dl] * SCALE;   // SCALE * WqT[d][e]  (scale BEFORE split)
            __nv_bfloat16 hi, lo; split_bf(v, hi, lo);
            g_WqTHi[(size_t)(d0 + dl) * ID + e0 + c] = hi;
            g_WqTLo[(size_t)(d0 + dl) * ID + e0 + c] = lo;
        }
    }
}

// ===== Fused GEMM (512 threads, k-chunk 128, 4 iters): K = E@Wk^T then M = K@(SCALE*WqT)^T =====
#define NT     512
#define RB     272                          // row stride: 128 bf16 = 256 B + 16 pad
#define P1_A_H 0
#define P1_A_L (P1_A_H + 64 * RB)           // 17408
#define P1_B_H (P1_A_L + 64 * RB)           // 34816
#define P1_B_L (P1_B_H + 128 * RB)          // 69632
#define STAGE  (P1_B_L + 128 * RB)          // 104448
// phase-2 layout (reuses smem): A2 64x128 bf16 (272-B rows), B2 one k64 half (144-B rows)
#define A2_H   0
#define A2_L   (A2_H + 64 * RB)             // 17408
#define B2_H   (A2_L + 64 * RB)             // 34816
#define RB2B   144
#define B2_L   (B2_H + 256 * RB2B)          // 71680
#define GSMEM  (2 * STAGE)                  // 208896

__global__ __launch_bounds__(NT, 1)
void gemm_fused_kernel(const float* __restrict__ edg)   // [N, HD] fp32
{
    extern __shared__ char smem[];
    const uint32_t sbase = smem_u32(smem);

    const int tid  = threadIdx.x;
    const int lane = tid & 31;
    const int wid  = tid >> 5;            // 0..15
    const int wm   = wid & 3;             // 4 m-groups of 16 rows
    const int wn   = wid >> 2;            // 4 n-groups
    const int m0   = blockIdx.x * 64;
    const int gid  = lane >> 2;
    const int tig  = lane & 3;

    const uint32_t laneoff = (uint32_t)((lane & 15) * RB + (lane >> 4) * 16);
    const uint32_t aOffH = P1_A_H + (uint32_t)(wm * 16) * RB + laneoff;
    const uint32_t aOffL = P1_A_L + (uint32_t)(wm * 16) * RB + laneoff;
    const uint32_t bOffH = P1_B_H + (uint32_t)(wn * 32) * RB + laneoff;
    const uint32_t bOffL = P1_B_L + (uint32_t)(wn * 32) * RB + laneoff;

    float acc[4][4];                      // warp tile 16(m) x 32(n)
#pragma unroll
    for (int nt = 0; nt < 4; nt++)
#pragma unroll
        for (int q = 0; q < 4; q++) acc[nt][q] = 0.f;

    float4 ra[4];
    auto ldgA = [&](int kc) {
#pragma unroll
        for (int i = 0; i < 4; i++) {
            int idx = tid + i * NT; int r = idx >> 5, k4 = idx & 31;
            ra[i] = *reinterpret_cast<const float4*>(edg + (size_t)(m0 + r) * HD + kc + 4 * k4);
        }
    };
    auto stsA = [&](uint32_t bufbase) {
        uint32_t* sw = reinterpret_cast<uint32_t*>(smem + bufbase);
#pragma unroll
        for (int i = 0; i < 4; i++) {
            int idx = tid + i * NT; int r = idx >> 5, k4 = idx & 31;
            float4 v = ra[i];
            __nv_bfloat16 hx, lx, hy, ly, hz, lz, hw, lw;
            split_bf(v.x, hx, lx); split_bf(v.y, hy, ly);
            split_bf(v.z, hz, lz); split_bf(v.w, hw, lw);
            int w0 = (P1_A_H >> 2) + r * (RB >> 2) + 2 * k4;
            sw[w0]     = pack_bf2(hx, hy);
            sw[w0 + 1] = pack_bf2(hz, hw);
            int w1 = (P1_A_L >> 2) + r * (RB >> 2) + 2 * k4;
            sw[w1]     = pack_bf2(lx, ly);
            sw[w1 + 1] = pack_bf2(lz, lw);
        }
    };
    auto cpB = [&](uint32_t bufbase, int kc) {
#pragma unroll
        for (int i = 0; i < 4; i++) {
            int idx = tid + i * NT; int n = idx >> 4, c = idx & 15;
            cp16(sbase + bufbase + P1_B_H + (uint32_t)(n * RB + c * 16),
                 g_WkHi + (size_t)n * HD + kc + c * 8);
            cp16(sbase + bufbase + P1_B_L + (uint32_t)(n * RB + c * 16),
                 g_WkLo + (size_t)n * HD + kc + c * 8);
        }
        asm volatile("cp.async.commit_group;" ::: "memory");
    };

    // ---------------- phase 1 mainloop: 4 iterations of k=128 ----------------
    ldgA(0);
    stsA(0);
    cpB(0, 0);

    for (int it = 0; it < 4; ++it) {
        const uint32_t buf  = (uint32_t)(it & 1) * STAGE;
        const uint32_t nbuf = (uint32_t)((it & 1) ^ 1) * STAGE;

        __syncthreads();
        if (it < 3) {
            ldgA((it + 1) * 128);
            cpB(nbuf, (it + 1) * 128);
            asm volatile("cp.async.wait_group 1;" ::: "memory");
        } else {
            asm volatile("cp.async.wait_group 0;" ::: "memory");
        }
        __syncthreads();

        const uint32_t aBH = sbase + buf + aOffH;
        const uint32_t aBL = sbase + buf + aOffL;
        const uint32_t bBH = sbase + buf + bOffH;
        const uint32_t bBL = sbase + buf + bOffL;
#pragma unroll
        for (int ks = 0; ks < 8; ks++) {
            const uint32_t koff = ks * 32;
            uint32_t ah[4], al[4];
            ldsm4(aBH + koff, ah);
            ldsm4(aBL + koff, al);
#pragma unroll
            for (int ng = 0; ng < 2; ng++) {
                uint32_t bh[4], bl[4];
                ldsm4(bBH + (uint32_t)ng * 16 * RB + koff, bh);
                ldsm4(bBL + (uint32_t)ng * 16 * RB + koff, bl);
                mma16816(acc[2 * ng],     ah, bh[0], bh[2]);
                mma16816(acc[2 * ng],     ah, bl[0], bl[2]);
                mma16816(acc[2 * ng],     al, bh[0], bh[2]);
                mma16816(acc[2 * ng + 1], ah, bh[1], bh[3]);
                mma16816(acc[2 * ng + 1], ah, bl[1], bl[3]);
                mma16816(acc[2 * ng + 1], al, bh[1], bh[3]);
            }
        }

        if (it < 3) stsA(nbuf);
    }

    // ---------------- phase 2: M[64,256] = K_tile @ (SCALE*WqT)^T, B2 in 2 k64 halves ----------
    __syncthreads();

    auto cpB2 = [&](int half) {
#pragma unroll
        for (int i = 0; i < 4; i++) {
            int idx = tid + i * NT; int n = idx >> 3, h = idx & 7;
            cp16(sbase + B2_H + (uint32_t)(n * RB2B + h * 16),
                 g_WqTHi + (size_t)n * ID + half * 64 + h * 8);
            cp16(sbase + B2_L + (uint32_t)(n * RB2B + h * 16),
                 g_WqTLo + (size_t)n * ID + half * 64 + h * 8);
        }
        asm volatile("cp.async.commit_group;" ::: "memory");
    };
    cpB2(0);

    {
        uint32_t* sw = reinterpret_cast<uint32_t*>(smem);
        const int r0 = wm * 16 + gid;
#pragma unroll
        for (int nt = 0; nt < 4; nt++) {
            int col = wn * 32 + nt * 8 + tig * 2;
            __nv_bfloat16 h0, l0, h1, l1, h2, l2, h3, l3;
            split_bf(acc[nt][0], h0, l0); split_bf(acc[nt][1], h1, l1);
            split_bf(acc[nt][2], h2, l2); split_bf(acc[nt][3], h3, l3);
            sw[(A2_H >> 2) + r0 * (RB >> 2) + col / 2]       = pack_bf2(h0, h1);
            sw[(A2_L >> 2) + r0 * (RB >> 2) + col / 2]       = pack_bf2(l0, l1);
            sw[(A2_H >> 2) + (r0 + 8) * (RB >> 2) + col / 2] = pack_bf2(h2, h3);
            sw[(A2_L >> 2) + (r0 + 8) * (RB >> 2) + col / 2] = pack_bf2(l2, l3);
        }
    }
    asm volatile("cp.async.wait_group 0;" ::: "memory");
    __syncthreads();

    float macc[8][4];
#pragma unroll
    for (int nt = 0; nt < 8; nt++)
#pragma unroll
        for (int q = 0; q < 4; q++) macc[nt][q] = 0.f;

    const uint32_t laneoff2B = (uint32_t)((lane & 15) * RB2B + (lane >> 4) * 16);
    const uint32_t a2H = sbase + A2_H + (uint32_t)(wm * 16) * RB + laneoff;
    const uint32_t a2L = sbase + A2_L + (uint32_t)(wm * 16) * RB + laneoff;
    const uint32_t b2H = sbase + B2_H + (uint32_t)(wn * 64) * RB2B + laneoff2B;
    const uint32_t b2L = sbase + B2_L + (uint32_t)(wn * 64) * RB2B + laneoff2B;

    for (int half = 0; half < 2; ++half) {
#pragma unroll
        for (int ks = 0; ks < 4; ks++) {
            const uint32_t koffA = (uint32_t)(half * 128 + ks * 32);
            const uint32_t koffB = (uint32_t)(ks * 32);
            uint32_t ah[4], al[4];
            ldsm4(a2H + koffA, ah);
            ldsm4(a2L + koffA, al);
#pragma unroll
            for (int ng = 0; ng < 4; ng++) {
                uint32_t bh[4], bl[4];
                ldsm4(b2H + (uint32_t)ng * 16 * RB2B + koffB, bh);
                ldsm4(b2L + (uint32_t)ng * 16 * RB2B + koffB, bl);
                mma16816(macc[2 * ng],     ah, bh[0], bh[2]);
                mma16816(macc[2 * ng],     ah, bl[0], bl[2]);
                mma16816(macc[2 * ng],     al, bh[0], bh[2]);
                mma16816(macc[2 * ng + 1], ah, bh[1], bh[3]);
                mma16816(macc[2 * ng + 1], ah, bl[1], bl[3]);
                mma16816(macc[2 * ng + 1], al, bh[1], bh[3]);
            }
        }
        if (half == 0) {
            __syncthreads();
            cpB2(1);
            asm volatile("cp.async.wait_group 0;" ::: "memory");
            __syncthreads();
        }
    }

    {
        const int row0 = m0 + wm * 16 + gid;
#pragma unroll
        for (int nt = 0; nt < 8; nt++) {
            const int col = wn * 64 + nt * 8 + tig * 2;
            *reinterpret_cast<float2*>(g_M + (size_t)row0 * GD + col) =
                make_float2(macc[nt][0], macc[nt][1]);
            *reinterpret_cast<float2*>(g_M + (size_t)(row0 + 8) * GD + col) =
                make_float2(macc[nt][2], macc[nt][3]);
        }
    }
}

// ========== Kernel B: batched streaming + warp transpose-reduce + masked softmax ===============
#define JB2 8

__global__ __launch_bounds__(256)
void cal_sim_stream_kernel(const float* __restrict__ chg,          // [B, N, GD]
                           const unsigned int* __restrict__ maskw, // [B, N] dtype probed
                           float* __restrict__ out)                // [N, B]
{
    __shared__ float s_M[JB2 * GD];

    const int t    = threadIdx.x;
    const int lane = t & 31;
    const int warp = t >> 5;            // 0..7 == jr
    const int j0   = blockIdx.x * JB2;

#pragma unroll
    for (int i = 0; i < 2; i++) {
        int idx = t + i * 256;
        *reinterpret_cast<float4*>(s_M + 4 * idx) =
            *reinterpret_cast<const float4*>(g_M + (size_t)j0 * GD + 4 * idx);
    }
    __syncthreads();

    float4 m0 = reinterpret_cast<const float4*>(s_M + warp * GD)[2 * lane];
    float4 m1 = reinterpret_cast<const float4*>(s_M + warp * GD)[2 * lane + 1];

    const float* crow = chg + (size_t)(j0 + warp) * GD + 8 * lane;

    // ---- batched streaming: 64 independent LDG.128, partials per b in registers ----
    float part[BB];
#pragma unroll
    for (int b = 0; b < BB; b++) {
        const float4* c = reinterpret_cast<const float4*>(crow + (size_t)b * NTOK * GD);
        float4 c0 = c[0];
        float4 c1 = c[1];
        part[b] = c0.x * m0.x + c0.y * m0.y + c0.z * m0.z + c0.w * m0.w
                + c1.x * m1.x + c1.y * m1.y + c1.z * m1.z + c1.w * m1.w;
    }

    // ---- warp transpose-reduce: 31 shfl; afterwards lane l holds full sim[b=l][j0+warp] ----
#pragma unroll
    for (int off = 16; off; off >>= 1) {
#pragma unroll
        for (int b = 0; b < off; b++) {
            float lo = part[b];
            float up = part[b + off];
            float keep = (lane & off) ? up : lo;
            float give = (lane & off) ? lo : up;
            part[b] = keep + __shfl_xor_sync(0xffffffffu, give, off);
        }
    }
    float v = part[0];   // sim for b == lane, row j0 + warp

    // ---- mask dtype probe ----
    bool notint = false, notfloat = false;
    for (int i = lane; i < 256; i += 32) {
        unsigned int w = maskw[i];
        notint   |= (w > 1u);
        notfloat |= (w != 0u && w != 0x3f800000u);
    }
    notint   = __any_sync(0xffffffffu, notint);
    notfloat = __any_sync(0xffffffffu, notfloat);
    const int mode = notint ? (notfloat ? 1 : 2) : 0;   // 0=int32, 1=byte, 2=float32

    // ---- masked softmax over b (lane == b) ----
    {
        const int jg = j0 + warp;
        bool mk;
        if (mode == 0)      mk = reinterpret_cast<const int*>(maskw)[(size_t)lane * NTOK + jg] != 0;
        else if (mode == 1) mk = reinterpret_cast<const unsigned char*>(maskw)[(size_t)lane * NTOK + jg] != 0;
        else                mk = reinterpret_cast<const float*>(maskw)[(size_t)lane * NTOK + jg] != 0.0f;
        v = mk ? v : -1e9f;
        float mx = v;
#pragma unroll
        for (int s = 16; s; s >>= 1) mx = fmaxf(mx, __shfl_xor_sync(0xffffffffu, mx, s));
        float ev = expf(v - mx);
        float sum = ev;
#pragma unroll
        for (int s = 16; s; s >>= 1) sum += __shfl_xor_sync(0xffffffffu, sum, s);
        out[(size_t)jg * BB + lane] = ev / sum;
    }
}

extern "C" void kernel_launch(void* const* d_in, const int* in_sizes, int n_in,
                              void* d_out, int out_size)
{
    const float*        chg  = (const float*)d_in[0];        // change_embeddings [B,N,256]
    const float*        edg  = (const float*)d_in[1];        // edges_embeddings  [N,512]
    const unsigned int* mask = (const unsigned int*)d_in[2]; // mask [B,N]
    const float*        Wq   = (const float*)d_in[3];        // [128,256]
    const float*        Wk   = (const float*)d_in[4];        // [128,512]
    float*              out  = (float*)d_out;                // [N,B]

    cudaFuncSetAttribute(gemm_fused_kernel,
                         cudaFuncAttributeMaxDynamicSharedMemorySize, GSMEM);

    prep_split_kernel<<<96, 256>>>(Wq, Wk);
    gemm_fused_kernel<<<NTOK / 64, NT, GSMEM>>>(edg);
    cal_sim_stream_kernel<<<NTOK / JB2, 256>>>(chg, mask, out);
}

// round 17
// speedup vs baseline: 1.0847x; 1.0847x over previous
#include <cuda_runtime.h>
#include <cuda_bf16.h>
#include <cstddef>
#include <cstdint>

// Problem constants
#define NTOK 8192   // N
#define BB   32     // batch
#define GD   256    // GRU_DIM
#define HD   512    // HAN_DIM
#define ID   128    // INNER_DIM

// ---------------- device scratch (no allocation) ----------------
__device__ float         g_M[NTOK * GD];      // 8 MB: M[j,d]
__device__ __nv_bfloat16 g_WkHi[ID * HD];     // 128 KB: Wk[e,h] hi (k-contig rows)
__device__ __nv_bfloat16 g_WkLo[ID * HD];     // 128 KB
__device__ __nv_bfloat16 g_WqTHi[GD * ID];    // 64 KB: SCALE * WqT[d,e] hi (k-contig rows)
__device__ __nv_bfloat16 g_WqTLo[GD * ID];    // 64 KB

__device__ __forceinline__ uint32_t smem_u32(const void* p) {
    uint32_t a;
    asm("{ .reg .u64 t; cvta.to.shared.u64 t, %1; cvt.u32.u64 %0, t; }" : "=r"(a) : "l"(p));
    return a;
}
__device__ __forceinline__ void ldsm4(uint32_t addr, uint32_t* r) {
    asm volatile("ldmatrix.sync.aligned.m8n8.x4.shared.b16 {%0,%1,%2,%3}, [%4];"
                 : "=r"(r[0]), "=r"(r[1]), "=r"(r[2]), "=r"(r[3]) : "r"(addr));
}
__device__ __forceinline__ void mma16816(float* c, const uint32_t* a, uint32_t b0, uint32_t b1) {
    asm volatile(
        "mma.sync.aligned.m16n8k16.row.col.f32.bf16.bf16.f32 "
        "{%0,%1,%2,%3}, {%4,%5,%6,%7}, {%8,%9}, {%0,%1,%2,%3};"
        : "+f"(c[0]), "+f"(c[1]), "+f"(c[2]), "+f"(c[3])
        : "r"(a[0]), "r"(a[1]), "r"(a[2]), "r"(a[3]), "r"(b0), "r"(b1));
}
__device__ __forceinline__ uint32_t pack_bf2(__nv_bfloat16 lo16, __nv_bfloat16 hi16) {
    __nv_bfloat162 t; t.x = lo16; t.y = hi16;
    return *reinterpret_cast<uint32_t*>(&t);
}
__device__ __forceinline__ void cp16(uint32_t dst, const void* src) {
    asm volatile("cp.async.cg.shared.global [%0], [%1], 16;" :: "r"(dst), "l"(src) : "memory");
}
__device__ __forceinline__ void split_bf(float v, __nv_bfloat16& hi, __nv_bfloat16& lo) {
    hi = __float2bfloat16(v);
    lo = __float2bfloat16(v - __bfloat162float(hi));
}

// ======================= P: split Wk (64 blocks) + transpose/split SCALE*Wq (32 blocks) ========
__global__ __launch_bounds__(256)
void prep_split_kernel(const float* __restrict__ Wq, const float* __restrict__ Wk)
{
    const int tid = threadIdx.x;
    if (blockIdx.x < 64) {
        int idx = blockIdx.x * 256 + tid;               // float4 index, 16384 total
        float4 v = *reinterpret_cast<const float4*>(Wk + 4 * (size_t)idx);
        __nv_bfloat16 hx, lx, hy, ly, hz, lz, hw, lw;
        split_bf(v.x, hx, lx); split_bf(v.y, hy, ly);
        split_bf(v.z, hz, lz); split_bf(v.w, hw, lw);
        *reinterpret_cast<uint32_t*>(g_WkHi + 4 * (size_t)idx)     = pack_bf2(hx, hy);
        *reinterpret_cast<uint32_t*>(g_WkHi + 4 * (size_t)idx + 2) = pack_bf2(hz, hw);
        *reinterpret_cast<uint32_t*>(g_WkLo + 4 * (size_t)idx)     = pack_bf2(lx, ly);
        *reinterpret_cast<uint32_t*>(g_WkLo + 4 * (size_t)idx + 2) = pack_bf2(lz, lw);
    } else {
        __shared__ float s[32][33];
        const int b  = blockIdx.x - 64;   // 0..31
        const int e0 = (b & 3) * 32;
        const int d0 = (b >> 2) * 32;
        const int r  = tid >> 5;          // 0..7
        const int c  = tid & 31;
        const float SCALE = 0.08838834764831845f;  // 128^-0.5
#pragma unroll
        for (int i = 0; i < 4; i++)
            s[r + i * 8][c] = Wq[(size_t)(e0 + r + i * 8) * GD + d0 + c];   // s[e][d]
        __syncthreads();
#pragma unroll
        for (int i = 0; i < 4; i++) {
            int dl = r + i * 8;
            float v = s[c][dl] * SCALE;   // SCALE * WqT[d][e]  (scale BEFORE split)
            __nv_bfloat16 hi, lo; split_bf(v, hi, lo);
            g_WqTHi[(size_t)(d0 + dl) * ID + e0 + c] = hi;
            g_WqTLo[(size_t)(d0 + dl) * ID + e0 + c] = lo;
        }
    }
}

// ===== Fused GEMM (512 threads, k-chunk 128, 4 iters): K = E@Wk^T then M = K@(SCALE*WqT)^T =====
#define NT     512
#define RB     272                          // row stride: 128 bf16 = 256 B + 16 pad
#define P1_A_H 0
#define P1_A_L (P1_A_H + 64 * RB)           // 17408
#define P1_B_H (P1_A_L + 64 * RB)           // 34816
#define P1_B_L (P1_B_H + 128 * RB)          // 69632
#define STAGE  (P1_B_L + 128 * RB)          // 104448
// phase-2 layout: B2 entirely inside stage buffer 0 (prefetchable during it=3);
// A2 after it (tail 4 KB spills into buffer 1, written only after the mainloop).
#define RB2B   144
#define B2_H   0
#define B2_L   (B2_H + 256 * RB2B)          // 36864
#define A2_H   (B2_L + 256 * RB2B)          // 73728
#define A2_L   (A2_H + 64 * RB)             // 91136  (ends 108544)
#define GSMEM  (2 * STAGE)                  // 208896

__global__ __launch_bounds__(NT, 1)
void gemm_fused_kernel(const float* __restrict__ edg)   // [N, HD] fp32
{
    extern __shared__ char smem[];
    const uint32_t sbase = smem_u32(smem);

    const int tid  = threadIdx.x;
    const int lane = tid & 31;
    const int wid  = tid >> 5;            // 0..15
    const int wm   = wid & 3;             // 4 m-groups of 16 rows
    const int wn   = wid >> 2;            // 4 n-groups
    const int m0   = blockIdx.x * 64;
    const int gid  = lane >> 2;
    const int tig  = lane & 3;

    const uint32_t laneoff = (uint32_t)((lane & 15) * RB + (lane >> 4) * 16);
    const uint32_t aOffH = P1_A_H + (uint32_t)(wm * 16) * RB + laneoff;
    const uint32_t aOffL = P1_A_L + (uint32_t)(wm * 16) * RB + laneoff;
    const uint32_t bOffH = P1_B_H + (uint32_t)(wn * 32) * RB + laneoff;
    const uint32_t bOffL = P1_B_L + (uint32_t)(wn * 32) * RB + laneoff;

    float acc[4][4];                      // warp tile 16(m) x 32(n)
#pragma unroll
    for (int nt = 0; nt < 4; nt++)
#pragma unroll
        for (int q = 0; q < 4; q++) acc[nt][q] = 0.f;

    float4 ra[4];
    auto ldgA = [&](int kc) {
#pragma unroll
        for (int i = 0; i < 4; i++) {
            int idx = tid + i * NT; int r = idx >> 5, k4 = idx & 31;
            ra[i] = *reinterpret_cast<const float4*>(edg + (size_t)(m0 + r) * HD + kc + 4 * k4);
        }
    };
    auto stsA = [&](uint32_t bufbase) {
        uint32_t* sw = reinterpret_cast<uint32_t*>(smem + bufbase);
#pragma unroll
        for (int i = 0; i < 4; i++) {
            int idx = tid + i * NT; int r = idx >> 5, k4 = idx & 31;
            float4 v = ra[i];
            __nv_bfloat16 hx, lx, hy, ly, hz, lz, hw, lw;
            split_bf(v.x, hx, lx); split_bf(v.y, hy, ly);
            split_bf(v.z, hz, lz); split_bf(v.w, hw, lw);
            int w0 = (P1_A_H >> 2) + r * (RB >> 2) + 2 * k4;
            sw[w0]     = pack_bf2(hx, hy);
            sw[w0 + 1] = pack_bf2(hz, hw);
            int w1 = (P1_A_L >> 2) + r * (RB >> 2) + 2 * k4;
            sw[w1]     = pack_bf2(lx, ly);
            sw[w1 + 1] = pack_bf2(lz, lw);
        }
    };
    auto cpB = [&](uint32_t bufbase, int kc) {
#pragma unroll
        for (int i = 0; i < 4; i++) {
            int idx = tid + i * NT; int n = idx >> 4, c = idx & 15;
            cp16(sbase + bufbase + P1_B_H + (uint32_t)(n * RB + c * 16),
                 g_WkHi + (size_t)n * HD + kc + c * 8);
            cp16(sbase + bufbase + P1_B_L + (uint32_t)(n * RB + c * 16),
                 g_WkLo + (size_t)n * HD + kc + c * 8);
        }
        asm volatile("cp.async.commit_group;" ::: "memory");
    };
    auto cpB2 = [&](int half) {
        // 256 n-rows x 64 k bf16 = 2048 16B chunks per array, 4/thread
#pragma unroll
        for (int i = 0; i < 4; i++) {
            int idx = tid + i * NT; int n = idx >> 3, h = idx & 7;
            cp16(sbase + B2_H + (uint32_t)(n * RB2B + h * 16),
                 g_WqTHi + (size_t)n * ID + half * 64 + h * 8);
            cp16(sbase + B2_L + (uint32_t)(n * RB2B + h * 16),
                 g_WqTLo + (size_t)n * ID + half * 64 + h * 8);
        }
        asm volatile("cp.async.commit_group;" ::: "memory");
    };

    // ---------------- phase 1 mainloop: 4 iterations of k=128 ----------------
    ldgA(0);
    stsA(0);
    cpB(0, 0);

    for (int it = 0; it < 4; ++it) {
        const uint32_t buf  = (uint32_t)(it & 1) * STAGE;
        const uint32_t nbuf = (uint32_t)((it & 1) ^ 1) * STAGE;

        __syncthreads();
        if (it < 3) {
            ldgA((it + 1) * 128);
            cpB(nbuf, (it + 1) * 128);
            asm volatile("cp.async.wait_group 1;" ::: "memory");
        } else {
            // buffer 0 is dead (it=3 computes from buffer 1): prefetch WqT half 0 into it.
            cpB2(0);
            // groups retire in order: waiting to depth 1 guarantees cpB(3) is done,
            // while the just-committed cpB2 group may remain in flight.
            asm volatile("cp.async.wait_group 1;" ::: "memory");
        }
        __syncthreads();

        const uint32_t aBH = sbase + buf + aOffH;
        const uint32_t aBL = sbase + buf + aOffL;
        const uint32_t bBH = sbase + buf + bOffH;
        const uint32_t bBL = sbase + buf + bOffL;
#pragma unroll
        for (int ks = 0; ks < 8; ks++) {
            const uint32_t koff = ks * 32;
            uint32_t ah[4], al[4];
            ldsm4(aBH + koff, ah);
            ldsm4(aBL + koff, al);
#pragma unroll
            for (int ng = 0; ng < 2; ng++) {
                uint32_t bh[4], bl[4];
                ldsm4(bBH + (uint32_t)ng * 16 * RB + koff, bh);
                ldsm4(bBL + (uint32_t)ng * 16 * RB + koff, bl);
                mma16816(acc[2 * ng],     ah, bh[0], bh[2]);
                mma16816(acc[2 * ng],     ah, bl[0], bl[2]);
                mma16816(acc[2 * ng],     al, bh[0], bh[2]);
                mma16816(acc[2 * ng + 1], ah, bh[1], bh[3]);
                mma16816(acc[2 * ng + 1], ah, bl[1], bl[3]);
                mma16816(acc[2 * ng + 1], al, bh[1], bh[3]);
            }
        }

        if (it < 3) stsA(nbuf);
    }

    // ---------------- phase 2: M[64,256] = K_tile @ (SCALE*WqT)^T, B2 half 0 already in flight -
    __syncthreads();   // all phase-1 stage reads done

    // store K accs (fp32) as bf16 hi/lo into A2 (m row, e col)
    {
        uint32_t* sw = reinterpret_cast<uint32_t*>(smem);
        const int r0 = wm * 16 + gid;
#pragma unroll
        for (int nt = 0; nt < 4; nt++) {
            int col = wn * 32 + nt * 8 + tig * 2;
            __nv_bfloat16 h0, l0, h1, l1, h2, l2, h3, l3;
            split_bf(acc[nt][0], h0, l0); split_bf(acc[nt][1], h1, l1);
            split_bf(acc[nt][2], h2, l2); split_bf(acc[nt][3], h3, l3);
            sw[(A2_H >> 2) + r0 * (RB >> 2) + col / 2]       = pack_bf2(h0, h1);
            sw[(A2_L >> 2) + r0 * (RB >> 2) + col / 2]       = pack_bf2(l0, l1);
            sw[(A2_H >> 2) + (r0 + 8) * (RB >> 2) + col / 2] = pack_bf2(h2, h3);
            sw[(A2_L >> 2) + (r0 + 8) * (RB >> 2) + col / 2] = pack_bf2(l2, l3);
        }
    }
    asm volatile("cp.async.wait_group 0;" ::: "memory");   // B2 half 0 arrived
    __syncthreads();

    float macc[8][4];                     // warp tile 16(m) x 64(n)
#pragma unroll
    for (int nt = 0; nt < 8; nt++)
#pragma unroll
        for (int q = 0; q < 4; q++) macc[nt][q] = 0.f;

    const uint32_t laneoff2B = (uint32_t)((lane & 15) * RB2B + (lane >> 4) * 16);
    const uint32_t a2H = sbase + A2_H + (uint32_t)(wm * 16) * RB + laneoff;
    const uint32_t a2L = sbase + A2_L + (uint32_t)(wm * 16) * RB + laneoff;
    const uint32_t b2H = sbase + B2_H + (uint32_t)(wn * 64) * RB2B + laneoff2B;
    const uint32_t b2L = sbase + B2_L + (uint32_t)(wn * 64) * RB2B + laneoff2B;

    for (int half = 0; half < 2; ++half) {
#pragma unroll
        for (int ks = 0; ks < 4; ks++) {
            const uint32_t koffA = (uint32_t)(half * 128 + ks * 32);  // within 256-B A2 rows
            const uint32_t koffB = (uint32_t)(ks * 32);               // within 128-B B2 rows
            uint32_t ah[4], al[4];
            ldsm4(a2H + koffA, ah);
            ldsm4(a2L + koffA, al);
#pragma unroll
            for (int ng = 0; ng < 4; ng++) {
                uint32_t bh[4], bl[4];
                ldsm4(b2H + (uint32_t)ng * 16 * RB2B + koffB, bh);
                ldsm4(b2L + (uint32_t)ng * 16 * RB2B + koffB, bl);
                mma16816(macc[2 * ng],     ah, bh[0], bh[2]);
                mma16816(macc[2 * ng],     ah, bl[0], bl[2]);
                mma16816(macc[2 * ng],     al, bh[0], bh[2]);
                mma16816(macc[2 * ng + 1], ah, bh[1], bh[3]);
                mma16816(macc[2 * ng + 1], ah, bl[1], bl[3]);
                mma16816(macc[2 * ng + 1], al, bh[1], bh[3]);
            }
        }
        if (half == 0) {
            __syncthreads();            // half 0 consumed by all warps
            cpB2(1);
            asm volatile("cp.async.wait_group 0;" ::: "memory");
            __syncthreads();            // half 1 visible
        }
    }

    // epilogue: write fp32 M
    {
        const int row0 = m0 + wm * 16 + gid;
#pragma unroll
        for (int nt = 0; nt < 8; nt++) {
            const int col = wn * 64 + nt * 8 + tig * 2;
            *reinterpret_cast<float2*>(g_M + (size_t)row0 * GD + col) =
                make_float2(macc[nt][0], macc[nt][1]);
            *reinterpret_cast<float2*>(g_M + (size_t)(row0 + 8) * GD + col) =
                make_float2(macc[nt][2], macc[nt][3]);
        }
    }
}

// ======================= Kernel B: sim + masked softmax (R15 proven form) ======================
#define JB2 8

__global__ __launch_bounds__(256)
void cal_sim_stream_kernel(const float* __restrict__ chg,          // [B, N, GD]
                           const unsigned int* __restrict__ maskw, // [B, N] dtype probed
                           float* __restrict__ out)                // [N, B]
{
    __shared__ float s_M[JB2 * GD];
    __shared__ float s_sim[BB * 9];

    const int t    = threadIdx.x;
    const int lane = t & 31;
    const int warp = t >> 5;
    const int j0   = blockIdx.x * JB2;

#pragma unroll
    for (int i = 0; i < 2; i++) {
        int idx = t + i * 256;
        *reinterpret_cast<float4*>(s_M + 4 * idx) =
            *reinterpret_cast<const float4*>(g_M + (size_t)j0 * GD + 4 * idx);
    }
    __syncthreads();

    float4 m0 = reinterpret_cast<const float4*>(s_M + warp * GD)[2 * lane];
    float4 m1 = reinterpret_cast<const float4*>(s_M + warp * GD)[2 * lane + 1];

    const float* crow = chg + (size_t)(j0 + warp) * GD;

#pragma unroll 8
    for (int b = 0; b < BB; b++) {
        const float4* c = reinterpret_cast<const float4*>(crow + (size_t)b * NTOK * GD);
        float4 c0 = c[2 * lane];
        float4 c1 = c[2 * lane + 1];
        float part = c0.x * m0.x + c0.y * m0.y + c0.z * m0.z + c0.w * m0.w
                   + c1.x * m1.x + c1.y * m1.y + c1.z * m1.z + c1.w * m1.w;
#pragma unroll
        for (int s = 16; s; s >>= 1) part += __shfl_xor_sync(0xffffffffu, part, s);
        if (lane == 0) s_sim[b * 9 + warp] = part;
    }
    __syncthreads();

    bool notint = false, notfloat = false;
    for (int i = lane; i < 256; i += 32) {
        unsigned int w = maskw[i];
        notint   |= (w > 1u);
        notfloat |= (w != 0u && w != 0x3f800000u);
    }
    notint   = __any_sync(0xffffffffu, notint);
    notfloat = __any_sync(0xffffffffu, notfloat);
    const int mode = notint ? (notfloat ? 1 : 2) : 0;   // 0=int32, 1=byte, 2=float32

    {
        const int jg = j0 + warp;
        float v = s_sim[lane * 9 + warp];
        bool mk;
        if (mode == 0)      mk = reinterpret_cast<const int*>(maskw)[(size_t)lane * NTOK + jg] != 0;
        else if (mode == 1) mk = reinterpret_cast<const unsigned char*>(maskw)[(size_t)lane * NTOK + jg] != 0;
        else                mk = reinterpret_cast<const float*>(maskw)[(size_t)lane * NTOK + jg] != 0.0f;
        v = mk ? v : -1e9f;
        float mx = v;
#pragma unroll
        for (int s = 16; s; s >>= 1) mx = fmaxf(mx, __shfl_xor_sync(0xffffffffu, mx, s));
        float ev = expf(v - mx);
        float sum = ev;
#pragma unroll
        for (int s = 16; s; s >>= 1) sum += __shfl_xor_sync(0xffffffffu, sum, s);
        out[(size_t)jg * BB + lane] = ev / sum;
    }
}

extern "C" void kernel_launch(void* const* d_in, const int* in_sizes, int n_in,
                              void* d_out, int out_size)
{
    const float*        chg  = (const float*)d_in[0];        // change_embeddings [B,N,256]
    const float*        edg  = (const float*)d_in[1];        // edges_embeddings  [N,512]
    const unsigned int* mask = (const unsigned int*)d_in[2]; // mask [B,N]
    const float*        Wq   = (const float*)d_in[3];        // [128,256]
    const float*        Wk   = (const float*)d_in[4];        // [128,512]
    float*              out  = (float*)d_out;                // [N,B]

    cudaFuncSetAttribute(gemm_fused_kernel,
                         cudaFuncAttributeMaxDynamicSharedMemorySize, GSMEM);

    prep_split_kernel<<<96, 256>>>(Wq, Wk);
    gemm_fused_kernel<<<NTOK / 64, NT, GSMEM>>>(edg);
    cal_sim_stream_kernel<<<NTOK / JB2, 256>>>(chg, mask, out);
}